// round 1
// baseline (speedup 1.0000x reference)
#include <cuda_runtime.h>

#define BSZ   8
#define NPTS  4096
#define CIN   128
#define COUT  256
#define MCTR  1024
#define SSAMP 64

// Scratch (static device globals: no allocations allowed)
__device__ float g_pre[BSZ * NPTS * COUT];   // [b][n][o]  33.5 MB
__device__ int   g_fps[BSZ * MCTR];
__device__ int   g_idx[BSZ * MCTR * SSAMP];

// Exact reference arithmetic: squares then left-to-right sum, no FMA contraction.
__device__ __forceinline__ float d2_rn(float ax, float ay, float az,
                                       float bx, float by, float bz) {
    float dx = ax - bx, dy = ay - by, dz = az - bz;
    return __fadd_rn(__fadd_rn(__fmul_rn(dx, dx), __fmul_rn(dy, dy)),
                     __fmul_rn(dz, dz));
}

// ---------------------------------------------------------------------------
// 1) Furthest point sampling: one block per batch. 256 threads x 16 points
//    in registers. Matches jax scan semantics: idx[0]=0; for t=1..1023:
//    update mind with pts[idx[t-1]], idx[t]=argmax (first-max tie-break).
// ---------------------------------------------------------------------------
__global__ __launch_bounds__(256) void fps_kernel(const float* __restrict__ xyz) {
    const int b = blockIdx.x, tid = threadIdx.x;
    const float* p = xyz + b * NPTS * 3;

    float px[16], py[16], pz[16], mind[16];
#pragma unroll
    for (int k = 0; k < 16; k++) {
        int n = k * 256 + tid;
        px[k] = p[3 * n + 0];
        py[k] = p[3 * n + 1];
        pz[k] = p[3 * n + 2];
        mind[k] = 1e10f;
    }

    __shared__ float s_lx, s_ly, s_lz;
    __shared__ int   s_li;
    __shared__ float s_wv[8];
    __shared__ int   s_wi[8];

    if (tid == 0) { s_li = 0; g_fps[b * MCTR] = 0; }
    __syncthreads();

    const int lane = tid & 31, warp = tid >> 5;

    for (int t = 1; t < MCTR; t++) {
        int last = s_li;
        if (tid == (last & 255)) {
            int k = last >> 8;
            s_lx = px[k]; s_ly = py[k]; s_lz = pz[k];
        }
        __syncthreads();
        float lx = s_lx, ly = s_ly, lz = s_lz;

        float best = -1.0f; int bi = 0;
#pragma unroll
        for (int k = 0; k < 16; k++) {
            float d  = d2_rn(px[k], py[k], pz[k], lx, ly, lz);
            float md = fminf(mind[k], d);
            mind[k] = md;
            // ascending n within thread + strict > keeps lowest index on ties
            if (md > best) { best = md; bi = k * 256 + tid; }
        }
#pragma unroll
        for (int off = 16; off > 0; off >>= 1) {
            float ov = __shfl_down_sync(0xffffffffu, best, off);
            int   oi = __shfl_down_sync(0xffffffffu, bi,   off);
            if (ov > best || (ov == best && oi < bi)) { best = ov; bi = oi; }
        }
        if (lane == 0) { s_wv[warp] = best; s_wi[warp] = bi; }
        __syncthreads();
        if (tid == 0) {
            float Bv = s_wv[0]; int Iv = s_wi[0];
#pragma unroll
            for (int w = 1; w < 8; w++) {
                if (s_wv[w] > Bv || (s_wv[w] == Bv && s_wi[w] < Iv)) {
                    Bv = s_wv[w]; Iv = s_wi[w];
                }
            }
            s_li = Iv;
            g_fps[b * MCTR + t] = Iv;
        }
        __syncthreads();
    }
}

// ---------------------------------------------------------------------------
// 2) Ball query: one warp per (b,m) center. Ballot-ordered scan in ascending
//    point index; early exit once 64 found; pad with first in-ball index.
// ---------------------------------------------------------------------------
__global__ __launch_bounds__(256) void ballquery_kernel(const float* __restrict__ xyz) {
    const int tid = threadIdx.x, lane = tid & 31, w = tid >> 5;
    const int gw = blockIdx.x * 8 + w;
    const int b = gw >> 10, m = gw & (MCTR - 1);
    const float* p = xyz + b * NPTS * 3;

    const int ci = g_fps[b * MCTR + m];
    const float cx = p[3 * ci + 0], cy = p[3 * ci + 1], cz = p[3 * ci + 2];
    const float R2 = 0.1024f;  // matches jax f32 cast of python 0.32*0.32

    int cnt = 0, firstIdx = 0;
    int* dst = g_idx + (b * MCTR + m) * SSAMP;

    for (int c0 = 0; c0 < NPTS && cnt < SSAMP; c0 += 32) {
        int n = c0 + lane;
        float d = d2_rn(p[3 * n + 0], p[3 * n + 1], p[3 * n + 2], cx, cy, cz);
        bool in = d < R2;
        unsigned msk = __ballot_sync(0xffffffffu, in);
        if (cnt == 0 && msk) firstIdx = c0 + (__ffs(msk) - 1);
        if (in) {
            int pos = cnt + __popc(msk & ((1u << lane) - 1u));
            if (pos < SSAMP) dst[pos] = n;
        }
        cnt += __popc(msk);
    }
    for (int pos = cnt + lane; pos < SSAMP; pos += 32) dst[pos] = firstIdx;
}

// ---------------------------------------------------------------------------
// 3) Pointwise conv on ALL N points (16x fewer FLOPs than per-slot einsum):
//    pre[b][n][o] = sum_c feat[b][c][n] * W[o][c].
//    Tile: 64 n x 128 o, K-chunks of 32. 256 threads, 4x8 microtile.
// ---------------------------------------------------------------------------
__global__ __launch_bounds__(256) void gemm_kernel(const float* __restrict__ feat,
                                                   const float* __restrict__ W) {
    const int b  = blockIdx.z;
    const int n0 = blockIdx.x * 64;
    const int o0 = blockIdx.y * 128;

    __shared__ float sF[32][65];    // [c][n]
    __shared__ float sW[32][129];   // [c][o]

    const int tid = threadIdx.x;
    const int tx = tid & 15;        // n group (x4)
    const int ty = tid >> 4;        // o group (x8)

    float acc[4][8];
#pragma unroll
    for (int i = 0; i < 4; i++)
#pragma unroll
        for (int j = 0; j < 8; j++) acc[i][j] = 0.f;

    const float* fb = feat + b * CIN * NPTS;

    for (int k0 = 0; k0 < CIN; k0 += 32) {
#pragma unroll
        for (int i = 0; i < 8; i++) {       // 32x64 feat tile
            int e = tid + i * 256;
            sF[e >> 6][e & 63] = fb[(k0 + (e >> 6)) * NPTS + n0 + (e & 63)];
        }
#pragma unroll
        for (int i = 0; i < 16; i++) {      // 128x32 W tile, stored [c][o]
            int e = tid + i * 256;
            sW[e & 31][e >> 5] = W[(o0 + (e >> 5)) * CIN + k0 + (e & 31)];
        }
        __syncthreads();
#pragma unroll
        for (int c = 0; c < 32; c++) {
            float fv[4], wv[8];
#pragma unroll
            for (int i = 0; i < 4; i++) fv[i] = sF[c][tx * 4 + i];
#pragma unroll
            for (int j = 0; j < 8; j++) wv[j] = sW[c][ty * 8 + j];
#pragma unroll
            for (int i = 0; i < 4; i++)
#pragma unroll
                for (int j = 0; j < 8; j++) acc[i][j] += fv[i] * wv[j];
        }
        __syncthreads();
    }

    float* pb = g_pre + b * NPTS * COUT;
#pragma unroll
    for (int i = 0; i < 4; i++) {
        int n = n0 + tx * 4 + i;
#pragma unroll
        for (int j = 0; j < 8; j++)
            pb[n * COUT + o0 + ty * 8 + j] = acc[i][j];
    }
}

// ---------------------------------------------------------------------------
// 4) Max-gather + folded BN/bias/ReLU (positive BN scale => max commutes).
//    One block per (b,m); thread o reduces over 64 neighbor columns.
// ---------------------------------------------------------------------------
__global__ __launch_bounds__(256) void maxpool_kernel(
    const float* __restrict__ bconv, const float* __restrict__ gamma,
    const float* __restrict__ beta,  const float* __restrict__ rmean,
    const float* __restrict__ rvar,  float* __restrict__ out) {
    const int m = blockIdx.x, b = blockIdx.y, o = threadIdx.x;

    __shared__ int sIdx[SSAMP];
    if (o < SSAMP) sIdx[o] = g_idx[(b * MCTR + m) * SSAMP + o];
    __syncthreads();

    const float* pb = g_pre + b * NPTS * COUT;
    float mx = -3.4e38f;
#pragma unroll 8
    for (int s = 0; s < SSAMP; s++)
        mx = fmaxf(mx, pb[sIdx[s] * COUT + o]);

    float inv = rsqrtf(rvar[o] + 1e-5f);
    float a = gamma[o] * inv;
    float v = (mx + bconv[o] - rmean[o]) * a + beta[o];
    out[(b * COUT + o) * MCTR + m] = fmaxf(v, 0.f);
}

// ---------------------------------------------------------------------------
extern "C" void kernel_launch(void* const* d_in, const int* in_sizes, int n_in,
                              void* d_out, int out_size) {
    const float* xyz  = (const float*)d_in[0];
    const float* feat = (const float*)d_in[1];
    const float* W    = (const float*)d_in[2];
    const float* bcv  = (const float*)d_in[3];
    const float* gm   = (const float*)d_in[4];
    const float* bt   = (const float*)d_in[5];
    const float* rm   = (const float*)d_in[6];
    const float* rv   = (const float*)d_in[7];
    float* out = (float*)d_out;

    fps_kernel<<<BSZ, 256>>>(xyz);
    ballquery_kernel<<<(BSZ * MCTR) / 8, 256>>>(xyz);
    gemm_kernel<<<dim3(NPTS / 64, COUT / 128, BSZ), 256>>>(feat, W);
    maxpool_kernel<<<dim3(MCTR, BSZ), 256>>>(bcv, gm, bt, rm, rv, out);
}

// round 4
// speedup vs baseline: 1.5136x; 1.5136x over previous
#include <cuda_runtime.h>

#define BSZ   8
#define NPTS  4096
#define CIN   128
#define COUT  256
#define MCTR  1024
#define SSAMP 64

// Scratch (static device globals: no allocations allowed)
__device__ float g_pre[BSZ * NPTS * COUT];   // [b][n][o]  33.5 MB
__device__ int   g_fps[BSZ * MCTR];
__device__ int   g_idx[BSZ * MCTR * SSAMP];

// Exact reference arithmetic: squares then left-to-right sum, no FMA contraction.
__device__ __forceinline__ float d2_rn(float ax, float ay, float az,
                                       float bx, float by, float bz) {
    float dx = ax - bx, dy = ay - by, dz = az - bz;
    return __fadd_rn(__fadd_rn(__fmul_rn(dx, dx), __fmul_rn(dy, dy)),
                     __fmul_rn(dz, dz));
}

// ---------------------------------------------------------------------------
// FPS body: 256 threads x 16 points in registers (statically indexed only —
// no local-memory demotion). Winner coordinates are re-read from global xyz
// (L1-resident after iter 1) by lane 0, avoiding any big smem mirror.
// Argmax: strict-> per thread (lowest idx on tie), then REDUX max on float
// bits (candidates are >= +0.0 or the -1.0 sentinel, so signed-int order ==
// value order), then REDUX min on index among attaining lanes.
// ---------------------------------------------------------------------------
__device__ void fps_body(const float* __restrict__ xyz, int b) {
    const int tid = threadIdx.x;
    const int lane = tid & 31, warp = tid >> 5;

    __shared__ float s_last[3];
    __shared__ int   s_wb[8];
    __shared__ int   s_wi[8];

    const float* p = xyz + b * NPTS * 3;

    float px[16], py[16], pz[16], mind[16];
#pragma unroll
    for (int k = 0; k < 16; k++) {
        int n = k * 256 + tid;
        px[k] = p[3 * n + 0];
        py[k] = p[3 * n + 1];
        pz[k] = p[3 * n + 2];
        mind[k] = 1e10f;
    }
    if (tid == 0) {
        s_last[0] = p[0]; s_last[1] = p[1]; s_last[2] = p[2];
        g_fps[b * MCTR] = 0;
    }
    __syncthreads();

    for (int t = 1; t < MCTR; t++) {
        const float lx = s_last[0], ly = s_last[1], lz = s_last[2];

        float best = -1.0f; int bi = 0;
#pragma unroll
        for (int k = 0; k < 16; k++) {
            float d  = d2_rn(px[k], py[k], pz[k], lx, ly, lz);
            float md = fminf(mind[k], d);
            mind[k] = md;
            if (md > best) { best = md; bi = k * 256 + tid; }  // ascending n: lowest idx on tie
        }

        int bb   = __float_as_int(best);
        int wmax = __reduce_max_sync(0xffffffffu, bb);
        int cand = (bb == wmax) ? bi : 0x7fffffff;
        int wbi  = __reduce_min_sync(0xffffffffu, cand);
        if (lane == 0) { s_wb[warp] = wmax; s_wi[warp] = wbi; }
        __syncthreads();

        if (warp == 0) {
            int vb = (lane < 8) ? s_wb[lane] : (int)0x80000000;
            int vi = (lane < 8) ? s_wi[lane] : 0x7fffffff;
            int m2 = __reduce_max_sync(0xffffffffu, vb);
            int c2 = (vb == m2) ? vi : 0x7fffffff;
            int Iv = __reduce_min_sync(0xffffffffu, c2);
            if (lane == 0) {
                // Winner coords straight from global (L1 hit) — same stored
                // bits as the register copy, so results are bit-identical.
                s_last[0] = p[3 * Iv + 0];
                s_last[1] = p[3 * Iv + 1];
                s_last[2] = p[3 * Iv + 2];
                g_fps[b * MCTR + t] = Iv;
            }
        }
        __syncthreads();
    }
}

// ---------------------------------------------------------------------------
// GEMM body: pre[b][n][o] = sum_c feat[b][c][n] * W[o][c].
// Tile: 64 n x 128 o, K-chunks of 32. 256 threads, 4x8 microtile.
// Static smem only (~24.9 KB including the FPS path's 76 B).
// ---------------------------------------------------------------------------
__device__ void gemm_body(const float* __restrict__ feat,
                          const float* __restrict__ W, int gid) {
    const int b    = gid >> 7;
    const int rest = gid & 127;
    const int o0   = (rest & 1) * 128;
    const int n0   = (rest >> 1) * 64;

    __shared__ float sF[32][65];
    __shared__ float sW[32][129];

    const int tid = threadIdx.x;
    const int tx = tid & 15;            // n group (x4)
    const int ty = tid >> 4;            // o group (x8)

    float acc[4][8];
#pragma unroll
    for (int i = 0; i < 4; i++)
#pragma unroll
        for (int j = 0; j < 8; j++) acc[i][j] = 0.f;

    const float* fb = feat + b * CIN * NPTS;

    for (int k0 = 0; k0 < CIN; k0 += 32) {
#pragma unroll
        for (int i = 0; i < 8; i++) {       // 32x64 feat tile
            int e = tid + i * 256;
            sF[e >> 6][e & 63] = fb[(k0 + (e >> 6)) * NPTS + n0 + (e & 63)];
        }
#pragma unroll
        for (int i = 0; i < 16; i++) {      // 128x32 W tile, stored [c][o]
            int e = tid + i * 256;
            sW[e & 31][e >> 5] = W[(o0 + (e >> 5)) * CIN + k0 + (e & 31)];
        }
        __syncthreads();
#pragma unroll
        for (int c = 0; c < 32; c++) {
            float fv[4], wv[8];
#pragma unroll
            for (int i = 0; i < 4; i++) fv[i] = sF[c][tx * 4 + i];
#pragma unroll
            for (int j = 0; j < 8; j++) wv[j] = sW[c][ty * 8 + j];
#pragma unroll
            for (int i = 0; i < 4; i++)
#pragma unroll
                for (int j = 0; j < 8; j++) acc[i][j] += fv[i] * wv[j];
        }
        __syncthreads();
    }

    float* pb = g_pre + b * NPTS * COUT;
#pragma unroll
    for (int i = 0; i < 4; i++) {
        int n = n0 + tx * 4 + i;
#pragma unroll
        for (int j = 0; j < 8; j++)
            pb[n * COUT + o0 + ty * 8 + j] = acc[i][j];
    }
}

// ---------------------------------------------------------------------------
// Fused launch: blocks 0..7 -> FPS (one per batch), blocks 8..1031 -> GEMM.
// Independent work; GEMM hides under the serial FPS with zero stream tricks.
// ---------------------------------------------------------------------------
__global__ __launch_bounds__(256) void fused_fps_gemm_kernel(
    const float* __restrict__ xyz, const float* __restrict__ feat,
    const float* __restrict__ W) {
    if (blockIdx.x < BSZ) fps_body(xyz, blockIdx.x);
    else                  gemm_body(feat, W, blockIdx.x - BSZ);
}

// ---------------------------------------------------------------------------
// Ball query: one warp per (b,m) center. Ballot-ordered ascending scan,
// early exit at 64 found, pad with first in-ball index.
// ---------------------------------------------------------------------------
__global__ __launch_bounds__(256) void ballquery_kernel(const float* __restrict__ xyz) {
    const int tid = threadIdx.x, lane = tid & 31, w = tid >> 5;
    const int gw = blockIdx.x * 8 + w;
    const int b = gw >> 10, m = gw & (MCTR - 1);
    const float* p = xyz + b * NPTS * 3;

    const int ci = g_fps[b * MCTR + m];
    const float cx = p[3 * ci + 0], cy = p[3 * ci + 1], cz = p[3 * ci + 2];
    const float R2 = 0.1024f;

    int cnt = 0, firstIdx = 0;
    int* dst = g_idx + (b * MCTR + m) * SSAMP;

    for (int c0 = 0; c0 < NPTS && cnt < SSAMP; c0 += 32) {
        int n = c0 + lane;
        float d = d2_rn(p[3 * n + 0], p[3 * n + 1], p[3 * n + 2], cx, cy, cz);
        bool in = d < R2;
        unsigned msk = __ballot_sync(0xffffffffu, in);
        if (cnt == 0 && msk) firstIdx = c0 + (__ffs(msk) - 1);
        if (in) {
            int pos = cnt + __popc(msk & ((1u << lane) - 1u));
            if (pos < SSAMP) dst[pos] = n;
        }
        cnt += __popc(msk);
    }
    for (int pos = cnt + lane; pos < SSAMP; pos += 32) dst[pos] = firstIdx;
}

// ---------------------------------------------------------------------------
// Max-gather + folded BN/bias/ReLU. 64 threads/block, float4 per thread,
// fully coalesced 16B loads.
// ---------------------------------------------------------------------------
__global__ __launch_bounds__(64) void maxpool_kernel(
    const float* __restrict__ bconv, const float* __restrict__ gamma,
    const float* __restrict__ beta,  const float* __restrict__ rmean,
    const float* __restrict__ rvar,  float* __restrict__ out) {
    const int m = blockIdx.x, b = blockIdx.y, tid = threadIdx.x;

    __shared__ int soff[SSAMP];
    soff[tid] = g_idx[(b * MCTR + m) * SSAMP + tid] * COUT;
    __syncthreads();

    const float* pb = g_pre + b * NPTS * COUT + tid * 4;
    float4 mx = make_float4(-3.4e38f, -3.4e38f, -3.4e38f, -3.4e38f);
#pragma unroll 8
    for (int s = 0; s < SSAMP; s++) {
        const float4 v = *(const float4*)(pb + soff[s]);
        mx.x = fmaxf(mx.x, v.x); mx.y = fmaxf(mx.y, v.y);
        mx.z = fmaxf(mx.z, v.z); mx.w = fmaxf(mx.w, v.w);
    }

    const float4 bc = ((const float4*)bconv)[tid];
    const float4 gm = ((const float4*)gamma)[tid];
    const float4 bt = ((const float4*)beta )[tid];
    const float4 rm = ((const float4*)rmean)[tid];
    const float4 rv = ((const float4*)rvar )[tid];

    const int o = tid * 4;
    out[(b * COUT + o + 0) * MCTR + m] =
        fmaxf((mx.x + bc.x - rm.x) * (gm.x * rsqrtf(rv.x + 1e-5f)) + bt.x, 0.f);
    out[(b * COUT + o + 1) * MCTR + m] =
        fmaxf((mx.y + bc.y - rm.y) * (gm.y * rsqrtf(rv.y + 1e-5f)) + bt.y, 0.f);
    out[(b * COUT + o + 2) * MCTR + m] =
        fmaxf((mx.z + bc.z - rm.z) * (gm.z * rsqrtf(rv.z + 1e-5f)) + bt.z, 0.f);
    out[(b * COUT + o + 3) * MCTR + m] =
        fmaxf((mx.w + bc.w - rm.w) * (gm.w * rsqrtf(rv.w + 1e-5f)) + bt.w, 0.f);
}

// ---------------------------------------------------------------------------
extern "C" void kernel_launch(void* const* d_in, const int* in_sizes, int n_in,
                              void* d_out, int out_size) {
    const float* xyz  = (const float*)d_in[0];
    const float* feat = (const float*)d_in[1];
    const float* W    = (const float*)d_in[2];
    const float* bcv  = (const float*)d_in[3];
    const float* gm   = (const float*)d_in[4];
    const float* bt   = (const float*)d_in[5];
    const float* rm   = (const float*)d_in[6];
    const float* rv   = (const float*)d_in[7];
    float* out = (float*)d_out;

    const int gemm_blocks = (NPTS / 64) * (COUT / 128) * BSZ;  // 1024
    fused_fps_gemm_kernel<<<BSZ + gemm_blocks, 256>>>(xyz, feat, W);
    ballquery_kernel<<<(BSZ * MCTR) / 8, 256>>>(xyz);
    maxpool_kernel<<<dim3(MCTR, BSZ), 64>>>(bcv, gm, bt, rm, rv, out);
}

// round 5
// speedup vs baseline: 1.6050x; 1.0604x over previous
#include <cuda_runtime.h>

#define BSZ   8
#define NPTS  4096
#define CIN   128
#define COUT  256
#define MCTR  1024
#define SSAMP 64

// Scratch (static device globals: no allocations allowed)
__device__ float g_pre[BSZ * NPTS * COUT];   // [b][n][o]  33.5 MB
__device__ int   g_fps[BSZ * MCTR];
__device__ int   g_idx[BSZ * MCTR * SSAMP];

// Exact reference arithmetic: squares then left-to-right sum, no FMA contraction.
__device__ __forceinline__ float d2_rn(float ax, float ay, float az,
                                       float bx, float by, float bz) {
    float dx = ax - bx, dy = ay - by, dz = az - bz;
    return __fadd_rn(__fadd_rn(__fmul_rn(dx, dx), __fmul_rn(dy, dy)),
                     __fmul_rn(dz, dz));
}

// ---- packed f32x2 helpers (per-lane IEEE rn: bit-identical to scalar) ----
__device__ __forceinline__ unsigned long long pack2(float lo, float hi) {
    unsigned long long r;
    asm("mov.b64 %0, {%1, %2};" : "=l"(r) : "f"(lo), "f"(hi));
    return r;
}
__device__ __forceinline__ void unpack2(unsigned long long v, float& lo, float& hi) {
    asm("mov.b64 {%0, %1}, %2;" : "=f"(lo), "=f"(hi) : "l"(v));
}
__device__ __forceinline__ unsigned long long add2(unsigned long long a,
                                                   unsigned long long b) {
    unsigned long long r;
    asm("add.rn.f32x2 %0, %1, %2;" : "=l"(r) : "l"(a), "l"(b));
    return r;
}
__device__ __forceinline__ unsigned long long mul2(unsigned long long a,
                                                   unsigned long long b) {
    unsigned long long r;
    asm("mul.rn.f32x2 %0, %1, %2;" : "=l"(r) : "l"(a), "l"(b));
    return r;
}

// ---------------------------------------------------------------------------
// FPS: 256 threads x 16 points, 2 points per packed f32x2 lane.
// Per iter: packed distance + scalar FMNMX mind update; scalar max-tree;
// REDUX value-only block max (every warp reduces the 8 warp maxima, so only
// 2 barriers); matching threads resolve the lowest index via atomicMin into
// a parity-double-buffered shared slot. Winner coords re-read from global
// (L1-resident broadcast). dx = px + (-lx) is bit-identical to px - lx.
// ---------------------------------------------------------------------------
__device__ void fps_body(const float* __restrict__ xyz, int b) {
    const int tid = threadIdx.x;
    const int lane = tid & 31, warp = tid >> 5;

    __shared__ int s_wv[8];
    __shared__ int s_widx[2];

    const float* p = xyz + b * NPTS * 3;

    unsigned long long px2[8], py2[8], pz2[8];
    float mind[16];
#pragma unroll
    for (int j = 0; j < 8; j++) {
        int n0 = (2 * j) * 256 + tid;
        int n1 = (2 * j + 1) * 256 + tid;
        px2[j] = pack2(p[3 * n0 + 0], p[3 * n1 + 0]);
        py2[j] = pack2(p[3 * n0 + 1], p[3 * n1 + 1]);
        pz2[j] = pack2(p[3 * n0 + 2], p[3 * n1 + 2]);
        mind[2 * j] = 1e10f; mind[2 * j + 1] = 1e10f;
    }
    if (tid == 0) s_widx[0] = 0;   // idx[0] = 0
    __syncthreads();

    for (int t = 1; t < MCTR; t++) {
        const int Iv = s_widx[(t - 1) & 1];
        if (tid == 0) {
            g_fps[b * MCTR + t - 1] = Iv;
            s_widx[t & 1] = 0x7fffffff;   // reset this iter's write slot
        }
        const float lx = __ldg(p + 3 * Iv + 0);
        const float ly = __ldg(p + 3 * Iv + 1);
        const float lz = __ldg(p + 3 * Iv + 2);
        const unsigned long long nlx2 = pack2(-lx, -lx);
        const unsigned long long nly2 = pack2(-ly, -ly);
        const unsigned long long nlz2 = pack2(-lz, -lz);

#pragma unroll
        for (int j = 0; j < 8; j++) {
            unsigned long long dx2 = add2(px2[j], nlx2);
            unsigned long long dy2 = add2(py2[j], nly2);
            unsigned long long dz2 = add2(pz2[j], nlz2);
            unsigned long long s2 = add2(add2(mul2(dx2, dx2), mul2(dy2, dy2)),
                                         mul2(dz2, dz2));
            float s0, s1; unpack2(s2, s0, s1);
            mind[2 * j]     = fminf(mind[2 * j],     s0);
            mind[2 * j + 1] = fminf(mind[2 * j + 1], s1);
        }

        // scalar max tree (values >= 0 -> int bit order == value order)
        float m01 = fmaxf(mind[0], mind[1]),   m23 = fmaxf(mind[2], mind[3]);
        float m45 = fmaxf(mind[4], mind[5]),   m67 = fmaxf(mind[6], mind[7]);
        float m89 = fmaxf(mind[8], mind[9]),   mab = fmaxf(mind[10], mind[11]);
        float mcd = fmaxf(mind[12], mind[13]), mef = fmaxf(mind[14], mind[15]);
        float q0 = fmaxf(m01, m23), q1 = fmaxf(m45, m67);
        float q2 = fmaxf(m89, mab), q3 = fmaxf(mcd, mef);
        float best = fmaxf(fmaxf(q0, q1), fmaxf(q2, q3));

        const int tb = __float_as_int(best);
        const int wmax = __reduce_max_sync(0xffffffffu, tb);
        if (lane == 0) s_wv[warp] = wmax;
        __syncthreads();

        // every warp redundantly reduces the 8 warp maxima (no extra barrier)
        int vb = (lane < 8) ? s_wv[lane] : (int)0x80000000;
        const int bmax = __reduce_max_sync(0xffffffffu, vb);

        if (tb == bmax) {  // rare: winner thread(s) resolve lowest index
            int n = 0x7fffffff;
#pragma unroll
            for (int k = 15; k >= 0; k--)
                if (__float_as_int(mind[k]) == bmax) n = k * 256 + tid;
            atomicMin(&s_widx[t & 1], n);
        }
        __syncthreads();
    }
    if (tid == 0) g_fps[b * MCTR + MCTR - 1] = s_widx[(MCTR - 1) & 1];
}

// ---------------------------------------------------------------------------
// GEMM body: pre[b][n][o] = sum_c feat[b][c][n] * W[o][c].
// Tile: 64 n x 128 o, K-chunks of 32. 256 threads, 4x8 microtile.
// ---------------------------------------------------------------------------
__device__ void gemm_body(const float* __restrict__ feat,
                          const float* __restrict__ W, int gid) {
    const int b    = gid >> 7;
    const int rest = gid & 127;
    const int o0   = (rest & 1) * 128;
    const int n0   = (rest >> 1) * 64;

    __shared__ float sF[32][65];
    __shared__ float sW[32][129];

    const int tid = threadIdx.x;
    const int tx = tid & 15;
    const int ty = tid >> 4;

    float acc[4][8];
#pragma unroll
    for (int i = 0; i < 4; i++)
#pragma unroll
        for (int j = 0; j < 8; j++) acc[i][j] = 0.f;

    const float* fb = feat + b * CIN * NPTS;

    for (int k0 = 0; k0 < CIN; k0 += 32) {
#pragma unroll
        for (int i = 0; i < 8; i++) {
            int e = tid + i * 256;
            sF[e >> 6][e & 63] = fb[(k0 + (e >> 6)) * NPTS + n0 + (e & 63)];
        }
#pragma unroll
        for (int i = 0; i < 16; i++) {
            int e = tid + i * 256;
            sW[e & 31][e >> 5] = W[(o0 + (e >> 5)) * CIN + k0 + (e & 31)];
        }
        __syncthreads();
#pragma unroll
        for (int c = 0; c < 32; c++) {
            float fv[4], wv[8];
#pragma unroll
            for (int i = 0; i < 4; i++) fv[i] = sF[c][tx * 4 + i];
#pragma unroll
            for (int j = 0; j < 8; j++) wv[j] = sW[c][ty * 8 + j];
#pragma unroll
            for (int i = 0; i < 4; i++)
#pragma unroll
                for (int j = 0; j < 8; j++) acc[i][j] += fv[i] * wv[j];
        }
        __syncthreads();
    }

    float* pb = g_pre + b * NPTS * COUT;
#pragma unroll
    for (int i = 0; i < 4; i++) {
        int n = n0 + tx * 4 + i;
#pragma unroll
        for (int j = 0; j < 8; j++)
            pb[n * COUT + o0 + ty * 8 + j] = acc[i][j];
    }
}

// ---------------------------------------------------------------------------
__global__ __launch_bounds__(256) void fused_fps_gemm_kernel(
    const float* __restrict__ xyz, const float* __restrict__ feat,
    const float* __restrict__ W) {
    if (blockIdx.x < BSZ) fps_body(xyz, blockIdx.x);
    else                  gemm_body(feat, W, blockIdx.x - BSZ);
}

// ---------------------------------------------------------------------------
// Ball query: one warp per (b,m) center. Ballot-ordered ascending scan,
// early exit at 64 found, pad with first in-ball index.
// ---------------------------------------------------------------------------
__global__ __launch_bounds__(256) void ballquery_kernel(const float* __restrict__ xyz) {
    const int tid = threadIdx.x, lane = tid & 31, w = tid >> 5;
    const int gw = blockIdx.x * 8 + w;
    const int b = gw >> 10, m = gw & (MCTR - 1);
    const float* p = xyz + b * NPTS * 3;

    const int ci = g_fps[b * MCTR + m];
    const float cx = p[3 * ci + 0], cy = p[3 * ci + 1], cz = p[3 * ci + 2];
    const float R2 = 0.1024f;

    int cnt = 0, firstIdx = 0;
    int* dst = g_idx + (b * MCTR + m) * SSAMP;

    for (int c0 = 0; c0 < NPTS && cnt < SSAMP; c0 += 32) {
        int n = c0 + lane;
        float d = d2_rn(p[3 * n + 0], p[3 * n + 1], p[3 * n + 2], cx, cy, cz);
        bool in = d < R2;
        unsigned msk = __ballot_sync(0xffffffffu, in);
        if (cnt == 0 && msk) firstIdx = c0 + (__ffs(msk) - 1);
        if (in) {
            int pos = cnt + __popc(msk & ((1u << lane) - 1u));
            if (pos < SSAMP) dst[pos] = n;
        }
        cnt += __popc(msk);
    }
    for (int pos = cnt + lane; pos < SSAMP; pos += 32) dst[pos] = firstIdx;
}

// ---------------------------------------------------------------------------
// Max-gather + folded BN/bias/ReLU. 64 threads/block, float4 per thread,
// fully coalesced 16B loads.
// ---------------------------------------------------------------------------
__global__ __launch_bounds__(64) void maxpool_kernel(
    const float* __restrict__ bconv, const float* __restrict__ gamma,
    const float* __restrict__ beta,  const float* __restrict__ rmean,
    const float* __restrict__ rvar,  float* __restrict__ out) {
    const int m = blockIdx.x, b = blockIdx.y, tid = threadIdx.x;

    __shared__ int soff[SSAMP];
    soff[tid] = g_idx[(b * MCTR + m) * SSAMP + tid] * COUT;
    __syncthreads();

    const float* pb = g_pre + b * NPTS * COUT + tid * 4;
    float4 mx = make_float4(-3.4e38f, -3.4e38f, -3.4e38f, -3.4e38f);
#pragma unroll 8
    for (int s = 0; s < SSAMP; s++) {
        const float4 v = *(const float4*)(pb + soff[s]);
        mx.x = fmaxf(mx.x, v.x); mx.y = fmaxf(mx.y, v.y);
        mx.z = fmaxf(mx.z, v.z); mx.w = fmaxf(mx.w, v.w);
    }

    const float4 bc = ((const float4*)bconv)[tid];
    const float4 gm = ((const float4*)gamma)[tid];
    const float4 bt = ((const float4*)beta )[tid];
    const float4 rm = ((const float4*)rmean)[tid];
    const float4 rv = ((const float4*)rvar )[tid];

    const int o = tid * 4;
    out[(b * COUT + o + 0) * MCTR + m] =
        fmaxf((mx.x + bc.x - rm.x) * (gm.x * rsqrtf(rv.x + 1e-5f)) + bt.x, 0.f);
    out[(b * COUT + o + 1) * MCTR + m] =
        fmaxf((mx.y + bc.y - rm.y) * (gm.y * rsqrtf(rv.y + 1e-5f)) + bt.y, 0.f);
    out[(b * COUT + o + 2) * MCTR + m] =
        fmaxf((mx.z + bc.z - rm.z) * (gm.z * rsqrtf(rv.z + 1e-5f)) + bt.z, 0.f);
    out[(b * COUT + o + 3) * MCTR + m] =
        fmaxf((mx.w + bc.w - rm.w) * (gm.w * rsqrtf(rv.w + 1e-5f)) + bt.w, 0.f);
}

// ---------------------------------------------------------------------------
extern "C" void kernel_launch(void* const* d_in, const int* in_sizes, int n_in,
                              void* d_out, int out_size) {
    const float* xyz  = (const float*)d_in[0];
    const float* feat = (const float*)d_in[1];
    const float* W    = (const float*)d_in[2];
    const float* bcv  = (const float*)d_in[3];
    const float* gm   = (const float*)d_in[4];
    const float* bt   = (const float*)d_in[5];
    const float* rm   = (const float*)d_in[6];
    const float* rv   = (const float*)d_in[7];
    float* out = (float*)d_out;

    const int gemm_blocks = (NPTS / 64) * (COUT / 128) * BSZ;  // 1024
    fused_fps_gemm_kernel<<<BSZ + gemm_blocks, 256>>>(xyz, feat, W);
    ballquery_kernel<<<(BSZ * MCTR) / 8, 256>>>(xyz);
    maxpool_kernel<<<dim3(MCTR, BSZ), 64>>>(bcv, gm, bt, rm, rv, out);
}